// round 7
// baseline (speedup 1.0000x reference)
#include <cuda_runtime.h>
#include <cstdint>
#include <cstddef>

#define NNODES 10000
#define NEDGES 640000
#define HID    128
#define OUTD   10

// Scratch: PQ[n][0:128] = x[n] @ W1[0:128,:]            (P)
//          PQ[n][128:256] = x[n] @ W1[128:256,:] + b1   (Q', b1 folded in)
__device__ float g_PQ[NNODES * 256];

// ---------- packed f32x2 helpers ----------
__device__ __forceinline__ unsigned long long f2_pack1(float v) {
    unsigned long long d;
    unsigned int u = __float_as_uint(v);
    asm("mov.b64 %0, {%1, %2};" : "=l"(d) : "r"(u), "r"(u));
    return d;
}
__device__ __forceinline__ unsigned long long f2_make(float a, float b) {
    unsigned long long d;
    unsigned int ua = __float_as_uint(a), ub = __float_as_uint(b);
    asm("mov.b64 %0, {%1, %2};" : "=l"(d) : "r"(ua), "r"(ub));
    return d;
}
__device__ __forceinline__ unsigned long long f2_fma(unsigned long long a,
                                                     unsigned long long b,
                                                     unsigned long long c) {
    unsigned long long d;
    asm("fma.rn.f32x2 %0, %1, %2, %3;" : "=l"(d) : "l"(a), "l"(b), "l"(c));
    return d;
}
__device__ __forceinline__ unsigned long long f2_add(unsigned long long a,
                                                     unsigned long long b) {
    unsigned long long d;
    asm("add.rn.f32x2 %0, %1, %2;" : "=l"(d) : "l"(a), "l"(b));
    return d;
}
__device__ __forceinline__ void f2_unpack(unsigned long long v, float& lo, float& hi) {
    unsigned int a, b;
    asm("mov.b64 {%0, %1}, %2;" : "=r"(a), "=r"(b) : "l"(v));
    lo = __uint_as_float(a);
    hi = __uint_as_float(b);
}

// ============================================================================
// Phase 1: PQ = x @ [W1a | W1b], b1 folded into the Q (second) half.
// ============================================================================
__global__ void __launch_bounds__(256) phase1_kernel(const float* __restrict__ x,
                                                     const float* __restrict__ W1,
                                                     const float* __restrict__ b1) {
    __shared__ float As[64][68];
    __shared__ float Bs[64][68];

    const int tid = threadIdx.x;
    const int m0 = blockIdx.x * 64;
    const int n0 = blockIdx.y * 64;
    const int tr = (tid >> 4) << 2;
    const int tc = (tid & 15) << 2;

    const int wRow = (n0 < 128) ? 0 : 128;
    const int wCol = (n0 < 128) ? n0 : (n0 - 128);

    float acc[4][4] = {};

    for (int k0 = 0; k0 < 128; k0 += 64) {
        #pragma unroll
        for (int i = 0; i < 4; i++) {
            int idx = tid + i * 256;
            int m = idx >> 4, kq = idx & 15;
            int gm = m0 + m;
            float4 v = make_float4(0.f, 0.f, 0.f, 0.f);
            if (gm < NNODES) v = *(const float4*)(x + (size_t)gm * HID + k0 + kq * 4);
            *(float4*)&As[m][kq * 4] = v;
        }
        #pragma unroll
        for (int i = 0; i < 4; i++) {
            int idx = tid + i * 256;
            int kk = idx >> 4, cq = idx & 15;
            float4 v = *(const float4*)(W1 + (size_t)(k0 + kk + wRow) * HID + wCol + cq * 4);
            *(float4*)&Bs[kk][cq * 4] = v;
        }
        __syncthreads();

        #pragma unroll
        for (int k = 0; k < 64; k++) {
            float4 b = *(const float4*)&Bs[k][tc];
            float a0 = As[tr + 0][k];
            float a1 = As[tr + 1][k];
            float a2 = As[tr + 2][k];
            float a3 = As[tr + 3][k];
            acc[0][0] += a0 * b.x; acc[0][1] += a0 * b.y; acc[0][2] += a0 * b.z; acc[0][3] += a0 * b.w;
            acc[1][0] += a1 * b.x; acc[1][1] += a1 * b.y; acc[1][2] += a1 * b.z; acc[1][3] += a1 * b.w;
            acc[2][0] += a2 * b.x; acc[2][1] += a2 * b.y; acc[2][2] += a2 * b.z; acc[2][3] += a2 * b.w;
            acc[3][0] += a3 * b.x; acc[3][1] += a3 * b.y; acc[3][2] += a3 * b.z; acc[3][3] += a3 * b.w;
        }
        __syncthreads();
    }

    float4 bv = make_float4(0.f, 0.f, 0.f, 0.f);
    if (n0 >= 128) bv = *(const float4*)(b1 + wCol + tc);

    #pragma unroll
    for (int r = 0; r < 4; r++) {
        int gm = m0 + tr + r;
        if (gm < NNODES) {
            *(float4*)(g_PQ + (size_t)gm * 256 + n0 + tc) =
                make_float4(acc[r][0] + bv.x, acc[r][1] + bv.y,
                            acc[r][2] + bv.z, acc[r][3] + bv.w);
        }
    }
}

// ============================================================================
// Phase 2 v5: register-resident W2 + reduce-scatter shuffle tree.
// Warp = 2 edges: half h = lane>>4, t = lane&15. Lane t owns j in
// {4t..4t+3} U {64+4t..64+4t+3}; W2 slice (8x5 f32x2) in registers.
// Gather: 4 LDG.128 / 2 edges (8 wavefronts/edge = floor for fp32).
// Reduce (reduce-scatter; SHFL.32 count per 2 edges = 14, was 28):
//   xor8: exchange 2 u64 (select-exchange) + 1 scalar (a4 split lo/hi)
//   xor4: exchange 1 u64 + 1 scalar -> lane owns out-pair c = t>>2
//   xor2, xor1: accumulate own r (u64) + g (scalar)
// b2 folded into accumulator init on lane t==0 (summed exactly once).
// Stores: (t&3)==0 -> float2 pair c; t==1 -> out[8]; t==9 -> out[9].
// ============================================================================
#define P2_THREADS 256
#define P2_ITERS 32
// edges/block = 8 warps * 32 iters * 2 = 512; grid = 1250

__global__ void __launch_bounds__(P2_THREADS, 2)
phase2_kernel(const int* __restrict__ ei,
              const float* __restrict__ W2,
              const float* __restrict__ b2,
              float* __restrict__ out) {
    const int tid  = threadIdx.x;
    const int lane = tid & 31;
    const int h    = lane >> 4;
    const int t    = lane & 15;
    const int c    = t >> 2;

    // Lane's W2 slice in registers (loaded once, reused for 64 edges)
    unsigned long long w[8][5];
    #pragma unroll
    for (int i = 0; i < 8; i++) {
        const int j = (i < 4) ? (4 * t + i) : (64 + 4 * t + (i - 4));
        const float* wr = W2 + j * OUTD;
        #pragma unroll
        for (int o2 = 0; o2 < 5; o2++)
            w[i][o2] = f2_make(wr[2 * o2], wr[2 * o2 + 1]);
    }

    // b2 folded into init accs on lane t==0 (counts once in the 16-lane sum)
    const bool lz = (t == 0);
    const unsigned long long i0 = lz ? f2_make(b2[0], b2[1]) : 0ull;
    const unsigned long long i1 = lz ? f2_make(b2[2], b2[3]) : 0ull;
    const unsigned long long i2 = lz ? f2_make(b2[4], b2[5]) : 0ull;
    const unsigned long long i3 = lz ? f2_make(b2[6], b2[7]) : 0ull;
    const unsigned long long i4 = lz ? f2_make(b2[8], b2[9]) : 0ull;

    const int e0 = blockIdx.x * 512 + (tid >> 5) * (P2_ITERS * 2);
    const float4* __restrict__ PQ4 = (const float4*)g_PQ;

    // Prologue gather (edge e0+h)
    int src = ei[e0 + h];
    int dst = ei[NEDGES + e0 + h];
    float4 p0 = PQ4[(size_t)src * 64 + t];
    float4 p1 = PQ4[(size_t)src * 64 + 16 + t];
    float4 q0 = PQ4[(size_t)dst * 64 + 32 + t];
    float4 q1 = PQ4[(size_t)dst * 64 + 48 + t];

    for (int it = 0; it < P2_ITERS; it++) {
        const int e = e0 + it * 2 + h;

        float hv[8];
        hv[0] = fmaxf(p0.x + q0.x, 0.f);
        hv[1] = fmaxf(p0.y + q0.y, 0.f);
        hv[2] = fmaxf(p0.z + q0.z, 0.f);
        hv[3] = fmaxf(p0.w + q0.w, 0.f);
        hv[4] = fmaxf(p1.x + q1.x, 0.f);
        hv[5] = fmaxf(p1.y + q1.y, 0.f);
        hv[6] = fmaxf(p1.z + q1.z, 0.f);
        hv[7] = fmaxf(p1.w + q1.w, 0.f);

        // Prefetch next edge's rows (p/q regs are dead now)
        if (it + 1 < P2_ITERS) {
            src = ei[e0 + (it + 1) * 2 + h];
            dst = ei[NEDGES + e0 + (it + 1) * 2 + h];
            p0 = PQ4[(size_t)src * 64 + t];
            p1 = PQ4[(size_t)src * 64 + 16 + t];
            q0 = PQ4[(size_t)dst * 64 + 32 + t];
            q1 = PQ4[(size_t)dst * 64 + 48 + t];
        }

        unsigned long long a0 = i0, a1 = i1, a2 = i2, a3 = i3, a4 = i4;
        #pragma unroll
        for (int i = 0; i < 8; i++) {
            unsigned long long vv = f2_pack1(hv[i]);
            a0 = f2_fma(vv, w[i][0], a0);
            a1 = f2_fma(vv, w[i][1], a1);
            a2 = f2_fma(vv, w[i][2], a2);
            a3 = f2_fma(vv, w[i][3], a3);
            a4 = f2_fma(vv, w[i][4], a4);
        }

        // ---- reduce-scatter over the 16-lane half ----
        // level xor8: t<8 keeps {a0,a1}, t>=8 keeps {a2,a3}
        unsigned long long s1 = (t < 8) ? a2 : a0;
        unsigned long long s2 = (t < 8) ? a3 : a1;
        unsigned long long r1v = __shfl_xor_sync(0xFFFFFFFFu, s1, 8);
        unsigned long long r2v = __shfl_xor_sync(0xFFFFFFFFu, s2, 8);
        unsigned long long t1 = f2_add((t < 8) ? a0 : a2, r1v);
        unsigned long long t2 = f2_add((t < 8) ? a1 : a3, r2v);
        // a4 split into scalars: t<8 accumulates o8, t>=8 accumulates o9
        float f8, f9;
        f2_unpack(a4, f8, f9);
        float gsend = (t < 8) ? f9 : f8;
        float gkeep = (t < 8) ? f8 : f9;
        float g = gkeep + __shfl_xor_sync(0xFFFFFFFFu, gsend, 8);

        // level xor4: t&4==0 keeps t1, t&4 keeps t2
        unsigned long long sd = (t & 4) ? t1 : t2;
        unsigned long long rv = __shfl_xor_sync(0xFFFFFFFFu, sd, 4);
        unsigned long long r = f2_add((t & 4) ? t2 : t1, rv);
        g += __shfl_xor_sync(0xFFFFFFFFu, g, 4);

        // levels xor2, xor1
        r = f2_add(r, __shfl_xor_sync(0xFFFFFFFFu, r, 2));
        g += __shfl_xor_sync(0xFFFFFFFFu, g, 2);
        r = f2_add(r, __shfl_xor_sync(0xFFFFFFFFu, r, 1));
        g += __shfl_xor_sync(0xFFFFFFFFu, g, 1);

        if ((t & 3) == 0) {
            float lo, hi;
            f2_unpack(r, lo, hi);
            *(float2*)(out + (size_t)e * OUTD + 2 * c) = make_float2(lo, hi);
        }
        if (t == 1) out[(size_t)e * OUTD + 8] = g;
        if (t == 9) out[(size_t)e * OUTD + 9] = g;
    }
}

// ============================================================================
extern "C" void kernel_launch(void* const* d_in, const int* in_sizes, int n_in,
                              void* d_out, int out_size) {
    const float* x  = (const float*)d_in[0];
    const int*   ei = (const int*)d_in[1];
    const float* W1 = (const float*)d_in[2];
    const float* b1 = (const float*)d_in[3];
    const float* W2 = (const float*)d_in[4];
    const float* b2 = (const float*)d_in[5];
    float* out = (float*)d_out;

    dim3 g1((NNODES + 63) / 64, 256 / 64);
    phase1_kernel<<<g1, 256>>>(x, W1, b1);

    phase2_kernel<<<1250, P2_THREADS>>>(ei, W2, b2, out);
}